// round 1
// baseline (speedup 1.0000x reference)
#include <cuda_runtime.h>
#include <math.h>

#define BATCH 32
#define A_AP 0.85f
#define A_DS 0.1f
#define CC1 (0.01f * 0.01f)
#define CC2 (0.03f * 0.03f)

// ---- static device scratch (no allocs allowed) ----
// pyramid levels 1..3 per side: 32*3*128*256 + 32*3*64*128 + 32*3*32*64
#define OFF_L1 0
#define OFF_L2 3145728
#define OFF_L3 3932160
#define PYR_TOT 4128768
__device__ float g_pyr_l[PYR_TOT];
__device__ float g_pyr_r[PYR_TOT];
// warped-estimate scratch, level-0 size
__device__ float g_est[32 * 3 * 256 * 512];
// accumulators: AP, LR, DS
__device__ double g_acc[3];

// -------------------- helpers --------------------
__device__ __forceinline__ float blockReduce(float v) {
    __shared__ float sh[32];
    int lane = threadIdx.x & 31;
    int wid = threadIdx.x >> 5;
    #pragma unroll
    for (int o = 16; o; o >>= 1) v += __shfl_down_sync(0xffffffffu, v, o);
    if (lane == 0) sh[wid] = v;
    __syncthreads();
    int nw = (blockDim.x + 31) >> 5;
    v = (threadIdx.x < nw) ? sh[lane] : 0.0f;
    if (wid == 0) {
        #pragma unroll
        for (int o = 16; o; o >>= 1) v += __shfl_down_sync(0xffffffffu, v, o);
    }
    return v;
}

__global__ void zero_acc_kernel() {
    if (threadIdx.x < 3) g_acc[threadIdx.x] = 0.0;
}

// bilinear align_corners resize (factor-2 cascade), [B,C,Hin,Win] -> [B,C,Hout,Wout]
__global__ void resize_kernel(const float* __restrict__ in, float* __restrict__ out,
                              int C, int Hin, int Win, int Hout, int Wout) {
    int idx = blockIdx.x * blockDim.x + threadIdx.x;
    int total = BATCH * C * Hout * Wout;
    if (idx >= total) return;
    int i = idx % Wout; int t = idx / Wout;
    int j = t % Hout;   t /= Hout;
    int c = t % C;      int b = t / C;

    float sy = (float)(Hin - 1) / (float)(Hout - 1);
    float sx = (float)(Win - 1) / (float)(Wout - 1);
    float y = j * sy, x = i * sx;
    int y0 = (int)floorf(y);
    int y1 = min(y0 + 1, Hin - 1);
    int x0 = (int)floorf(x);
    int x1 = min(x0 + 1, Win - 1);
    float wy = y - (float)y0;
    float wx = x - (float)x0;
    const float* p = in + ((long)(b * C + c) * Hin) * Win;
    float tl = p[y0 * Win + x0], tr = p[y0 * Win + x1];
    float bl = p[y1 * Win + x0], br = p[y1 * Win + x1];
    float top = tl * (1.f - wy) + bl * wy;
    float bot = tr * (1.f - wy) + br * wy;
    out[idx] = top * (1.f - wx) + bot * wx;
}

// horizontal-only bilinear gather (grid_sample degenerates since gy == exact row)
__device__ __forceinline__ float sample_x(const float* __restrict__ row, float x, int W) {
    float x0f = floorf(x);
    int x0 = (int)x0f;
    float w1 = x - x0f;
    float w0 = 1.f - w1;
    float v = 0.f;
    if (x0 >= 0 && x0 <= W - 1) v += row[x0] * w0;
    int x1 = x0 + 1;
    if (x1 >= 0 && x1 <= W - 1) v += row[x1] * w1;
    return v;
}

// est[b,c,j,i] = bilinear_x( img[b,c,j,:], i + sign*disp*(W-1) )
__global__ void warp_kernel(const float* __restrict__ img, const float* __restrict__ disp,
                            int dispChanOff, int dispBStride, float sign,
                            float* __restrict__ out, int C, int H, int W) {
    int idx = blockIdx.x * blockDim.x + threadIdx.x;
    int total = BATCH * C * H * W;
    if (idx >= total) return;
    int i = idx % W; int t = idx / W;
    int j = t % H;   t /= H;
    int c = t % C;   int b = t / C;

    float d = disp[(long)b * dispBStride + dispChanOff + j * W + i];
    float x = (float)i + sign * d * (float)(W - 1);
    const float* row = img + ((long)(b * C + c) * H + j) * W;
    out[idx] = sample_x(row, x, W);
}

// SSIM (3x3 VALID avgpool) + L1, fused reduction into g_acc[0]
__global__ void ssim_l1_kernel(const float* __restrict__ X, const float* __restrict__ Y,
                               int C, int H, int W, float coefS, float coefL) {
    int idx = blockIdx.x * blockDim.x + threadIdx.x;
    int total = BATCH * C * H * W;
    float acc = 0.f;
    if (idx < total) {
        int i = idx % W; int t = idx / W;
        int j = t % H;   t /= H;
        float xc = X[idx], yc = Y[idx];
        acc = coefL * fabsf(xc - yc);
        if (j >= 1 && j <= H - 2 && i >= 1 && i <= W - 2) {
            const float* Xp = X + (long)t * H * W;  // t == b*C+c
            const float* Yp = Y + (long)t * H * W;
            float sx = 0.f, sy = 0.f, sxx = 0.f, syy = 0.f, sxy = 0.f;
            #pragma unroll
            for (int dy = -1; dy <= 1; dy++) {
                const float* xr = Xp + (j + dy) * W + i;
                const float* yr = Yp + (j + dy) * W + i;
                #pragma unroll
                for (int dx = -1; dx <= 1; dx++) {
                    float xv = xr[dx], yv = yr[dx];
                    sx += xv; sy += yv;
                    sxx += xv * xv; syy += yv * yv; sxy += xv * yv;
                }
            }
            const float inv9 = 1.f / 9.f;
            float mux = sx * inv9, muy = sy * inv9;
            float sigx = sxx * inv9 - mux * mux;
            float sigy = syy * inv9 - muy * muy;
            float cov  = sxy * inv9 - mux * muy;
            float ssim = ((2.f * mux * muy + CC1) * (2.f * cov + CC2)) /
                         ((mux * mux + muy * muy + CC1) * (sigx + sigy + CC2));
            float v = (1.f - ssim) * 0.5f;
            v = fminf(fmaxf(v, 0.f), 1.f);
            acc += coefS * v;
        }
    }
    float s = blockReduce(acc);
    if (threadIdx.x == 0) atomicAdd(&g_acc[0], (double)s);
}

// LR consistency: |dl - warp(dr,-dl)| + |dr - warp(dl,+dr)|
__global__ void lr_kernel(const float* __restrict__ disp, int H, int W, float coef) {
    int idx = blockIdx.x * blockDim.x + threadIdx.x;
    int total = BATCH * H * W;
    float acc = 0.f;
    if (idx < total) {
        int i = idx % W; int t = idx / W;
        int j = t % H;   int b = t / H;
        const float* dlp = disp + (long)b * 2 * H * W;
        const float* drp = dlp + H * W;
        float dl = dlp[j * W + i];
        float dr = drp[j * W + i];
        float r2l = sample_x(drp + j * W, (float)i - dl * (float)(W - 1), W);
        float l2r = sample_x(dlp + j * W, (float)i + dr * (float)(W - 1), W);
        acc = fabsf(dl - r2l) + fabsf(dr - l2r);
    }
    float s = blockReduce(acc);
    if (threadIdx.x == 0) atomicAdd(&g_acc[1], (double)(coef * s));
}

// edge-aware smoothness for both disparity channels
__global__ void ds_kernel(const float* __restrict__ disp,
                          const float* __restrict__ lp, const float* __restrict__ rp,
                          int H, int W, float coef) {
    int idx = blockIdx.x * blockDim.x + threadIdx.x;
    int total = BATCH * H * W;
    float acc = 0.f;
    if (idx < total) {
        int i = idx % W; int t = idx / W;
        int j = t % H;   int b = t / H;
        long hw = (long)H * W;
        const float* dlp = disp + (long)b * 2 * hw;
        const float* drp = dlp + hw;
        const float* L = lp + (long)b * 3 * hw + (long)j * W + i;
        const float* R = rp + (long)b * 3 * hw + (long)j * W + i;
        int o = j * W + i;
        const float third = 1.f / 3.f;
        if (i < W - 1) {
            float aL = fabsf(L[0] - L[1]) + fabsf(L[hw] - L[hw + 1]) + fabsf(L[2 * hw] - L[2 * hw + 1]);
            float aR = fabsf(R[0] - R[1]) + fabsf(R[hw] - R[hw + 1]) + fabsf(R[2 * hw] - R[2 * hw + 1]);
            acc += fabsf(dlp[o] - dlp[o + 1]) * expf(-aL * third);
            acc += fabsf(drp[o] - drp[o + 1]) * expf(-aR * third);
        }
        if (j < H - 1) {
            float aL = fabsf(L[0] - L[W]) + fabsf(L[hw] - L[hw + W]) + fabsf(L[2 * hw] - L[2 * hw + W]);
            float aR = fabsf(R[0] - R[W]) + fabsf(R[hw] - R[hw + W]) + fabsf(R[2 * hw] - R[2 * hw + W]);
            acc += fabsf(dlp[o] - dlp[o + W]) * expf(-aL * third);
            acc += fabsf(drp[o] - drp[o + W]) * expf(-aR * third);
        }
    }
    float s = blockReduce(acc);
    if (threadIdx.x == 0) atomicAdd(&g_acc[2], (double)(coef * s));
}

__global__ void finalize_kernel(float* __restrict__ out) {
    float AP = (float)g_acc[0];
    float LR = (float)g_acc[1];
    float DS = (float)g_acc[2];
    out[0] = AP + LR + DS;
    out[1] = AP;
    out[2] = LR;
    out[3] = DS;
}

// -------------------- host --------------------
extern "C" void kernel_launch(void* const* d_in, const int* in_sizes, int n_in,
                              void* d_out, int out_size) {
    const float* disp[4];
    for (int i = 0; i < 4; i++) disp[i] = (const float*)d_in[i];
    const float* left = (const float*)d_in[4];
    const float* right = (const float*)d_in[5];

    float *pl, *pr, *est;
    cudaGetSymbolAddress((void**)&pl, g_pyr_l);
    cudaGetSymbolAddress((void**)&pr, g_pyr_r);
    cudaGetSymbolAddress((void**)&est, g_est);

    const int H = 256, W = 512;
    const int TB = 256;

    zero_acc_kernel<<<1, 32>>>();

    const float* lp[4];
    const float* rp[4];
    lp[0] = left; rp[0] = right;
    float* lbuf[4] = {nullptr, pl + OFF_L1, pl + OFF_L2, pl + OFF_L3};
    float* rbuf[4] = {nullptr, pr + OFF_L1, pr + OFF_L2, pr + OFF_L3};

    for (int i = 1; i < 4; i++) {
        int hin = H >> (i - 1), win = W >> (i - 1);
        int ho = H >> i, wo = W >> i;
        int tot = BATCH * 3 * ho * wo;
        int grid = (tot + TB - 1) / TB;
        resize_kernel<<<grid, TB>>>(lp[i - 1], lbuf[i], 3, hin, win, ho, wo);
        resize_kernel<<<grid, TB>>>(rp[i - 1], rbuf[i], 3, hin, win, ho, wo);
        lp[i] = lbuf[i];
        rp[i] = rbuf[i];
    }

    for (int i = 0; i < 4; i++) {
        int h = H >> i, w = W >> i;
        int totI = BATCH * 3 * h * w;
        int gI = (totI + TB - 1) / TB;
        int totD = BATCH * h * w;
        int gD = (totD + TB - 1) / TB;

        float coefS = (A_AP * A_AP) / ((float)BATCH * 3.f * (float)(h - 2) * (float)(w - 2));
        float coefL = (A_AP * (1.f - A_AP)) / (float)totI;

        // left_est = warp(rp, -dl); AP term vs lp
        warp_kernel<<<gI, TB>>>(rp[i], disp[i], 0, 2 * h * w, -1.f, est, 3, h, w);
        ssim_l1_kernel<<<gI, TB>>>(lp[i], est, 3, h, w, coefS, coefL);
        // right_est = warp(lp, +dr); AP term vs rp
        warp_kernel<<<gI, TB>>>(lp[i], disp[i], h * w, 2 * h * w, +1.f, est, 3, h, w);
        ssim_l1_kernel<<<gI, TB>>>(rp[i], est, 3, h, w, coefS, coefL);

        lr_kernel<<<gD, TB>>>(disp[i], h, w, 1.0f / (float)totD);
        ds_kernel<<<gD, TB>>>(disp[i], lp[i], rp[i], h, w, A_DS / ((float)totD * (float)(1 << i)));
    }

    finalize_kernel<<<1, 1>>>((float*)d_out);
}

// round 3
// speedup vs baseline: 1.0905x; 1.0905x over previous
#include <cuda_runtime.h>
#include <math.h>

#define BATCH 32
#define A_AP 0.85f
#define A_DS 0.1f
#define CC1 (0.01f * 0.01f)
#define CC2 (0.03f * 0.03f)

#define BX 32
#define BY 16
#define NTHR (BX * BY)
#define TLX (BX + 2)
#define TLY (BY + 2)
#define TILE (TLX * TLY)

// ---- static device scratch (no allocs allowed) ----
#define OFF_L1 0
#define OFF_L2 3145728
#define OFF_L3 3932160
#define PYR_TOT 4128768
__device__ float g_pyr_l[PYR_TOT];
__device__ float g_pyr_r[PYR_TOT];
// accumulators: AP, LR, DS
__device__ double g_acc[3];

// -------------------- helpers --------------------
__device__ __forceinline__ float blockReduce(float v) {
    __shared__ float sh[32];
    int lane = threadIdx.x & 31;
    int tid = threadIdx.y * blockDim.x + threadIdx.x;
    int wid = tid >> 5;
    lane = tid & 31;
    #pragma unroll
    for (int o = 16; o; o >>= 1) v += __shfl_down_sync(0xffffffffu, v, o);
    if (lane == 0) sh[wid] = v;
    __syncthreads();
    int nw = (blockDim.x * blockDim.y + 31) >> 5;
    v = (tid < nw) ? sh[tid] : 0.0f;
    if (wid == 0) {
        #pragma unroll
        for (int o = 16; o; o >>= 1) v += __shfl_down_sync(0xffffffffu, v, o);
    }
    return v;
}

__global__ void zero_acc_kernel() {
    if (threadIdx.x < 3) g_acc[threadIdx.x] = 0.0;
}

// bilinear align_corners resize (factor-2 cascade)
__global__ void resize_kernel(const float* __restrict__ in, float* __restrict__ out,
                              int C, int Hin, int Win, int Hout, int Wout) {
    int idx = blockIdx.x * blockDim.x + threadIdx.x;
    int total = BATCH * C * Hout * Wout;
    if (idx >= total) return;
    int i = idx % Wout; int t = idx / Wout;
    int j = t % Hout;   t /= Hout;
    int c = t % C;      int b = t / C;

    float sy = (float)(Hin - 1) / (float)(Hout - 1);
    float sx = (float)(Win - 1) / (float)(Wout - 1);
    float y = j * sy, x = i * sx;
    int y0 = (int)floorf(y);
    int y1 = min(y0 + 1, Hin - 1);
    int x0 = (int)floorf(x);
    int x1 = min(x0 + 1, Win - 1);
    float wy = y - (float)y0;
    float wx = x - (float)x0;
    const float* p = in + ((long)(b * C + c) * Hin) * Win;
    float tl = p[y0 * Win + x0], tr = p[y0 * Win + x1];
    float bl = p[y1 * Win + x0], br = p[y1 * Win + x1];
    float top = tl * (1.f - wy) + bl * wy;
    float bot = tr * (1.f - wy) + br * wy;
    out[idx] = top * (1.f - wx) + bot * wx;
}

// horizontal-only bilinear gather (grid_sample degenerates since gy == exact row)
__device__ __forceinline__ float sample_x(const float* __restrict__ row, float x, int W) {
    float x0f = floorf(x);
    int x0 = (int)x0f;
    float w1 = x - x0f;
    float w0 = 1.f - w1;
    float v = 0.f;
    if (x0 >= 0 && x0 <= W - 1) v += __ldg(row + x0) * w0;
    int x1 = x0 + 1;
    if (x1 >= 0 && x1 <= W - 1) v += __ldg(row + x1) * w1;
    return v;
}

// ---- fused: warp (on-the-fly) + SSIM(3x3 valid) + L1, per (b, tile), 3 channels ----
// est[b,c,j,i] = bilinear_x( img[b,c,j,:], i + sign*disp*(W-1) ); compare vs X
__global__ void fused_ap_kernel(const float* __restrict__ X, const float* __restrict__ img,
                                const float* __restrict__ disp, int chanOff,
                                float sign, int H, int W, float coefS, float coefL) {
    __shared__ float dsh[TILE];
    __shared__ float Es[TILE];
    __shared__ float Xs[TILE];

    int b = blockIdx.z;
    int ox = blockIdx.x * BX, oy = blockIdx.y * BY;
    int tid = threadIdx.y * BX + threadIdx.x;
    long hw = (long)H * W;
    const float* dptr = disp + (long)b * 2 * hw + chanOff;

    // load disp halo tile once
    for (int idx = tid; idx < TILE; idx += NTHR) {
        int lx = idx % TLX, ly = idx / TLX;
        int gx = ox - 1 + lx, gy = oy - 1 + ly;
        float d = 0.f;
        if (gx >= 0 && gx < W && gy >= 0 && gy < H) d = dptr[gy * W + gx];
        dsh[idx] = d;
    }
    __syncthreads();

    float acc = 0.f;
    #pragma unroll
    for (int c = 0; c < 3; c++) {
        const float* Xp = X + (long)(b * 3 + c) * hw;
        const float* Ip = img + (long)(b * 3 + c) * hw;
        for (int idx = tid; idx < TILE; idx += NTHR) {
            int lx = idx % TLX, ly = idx / TLX;
            int gx = ox - 1 + lx, gy = oy - 1 + ly;
            float e = 0.f, xv = 0.f;
            if (gx >= 0 && gx < W && gy >= 0 && gy < H) {
                xv = Xp[gy * W + gx];
                float xf = (float)gx + sign * dsh[idx] * (float)(W - 1);
                e = sample_x(Ip + (long)gy * W, xf, W);
            }
            Es[idx] = e;
            Xs[idx] = xv;
        }
        __syncthreads();

        int gx = ox + threadIdx.x, gy = oy + threadIdx.y;
        if (gx < W && gy < H) {
            int l = (threadIdx.y + 1) * TLX + (threadIdx.x + 1);
            acc += coefL * fabsf(Xs[l] - Es[l]);
            if (gx >= 1 && gx <= W - 2 && gy >= 1 && gy <= H - 2) {
                float sx = 0.f, sy = 0.f, sxx = 0.f, syy = 0.f, sxy = 0.f;
                #pragma unroll
                for (int dy = -1; dy <= 1; dy++) {
                    #pragma unroll
                    for (int dx = -1; dx <= 1; dx++) {
                        int l2 = l + dy * TLX + dx;
                        float xv = Xs[l2], yv = Es[l2];
                        sx += xv; sy += yv;
                        sxx += xv * xv; syy += yv * yv; sxy += xv * yv;
                    }
                }
                const float inv9 = 1.f / 9.f;
                float mux = sx * inv9, muy = sy * inv9;
                float sigx = sxx * inv9 - mux * mux;
                float sigy = syy * inv9 - muy * muy;
                float cov  = sxy * inv9 - mux * muy;
                float ssim = ((2.f * mux * muy + CC1) * (2.f * cov + CC2)) /
                             ((mux * mux + muy * muy + CC1) * (sigx + sigy + CC2));
                float v = (1.f - ssim) * 0.5f;
                v = fminf(fmaxf(v, 0.f), 1.f);
                acc += coefS * v;
            }
        }
        __syncthreads();
    }

    float s = blockReduce(acc);
    if (tid == 0) atomicAdd(&g_acc[0], (double)s);
}

// ---- fused LR consistency + edge-aware smoothness ----
__global__ void lrds_kernel(const float* __restrict__ disp,
                            const float* __restrict__ lp, const float* __restrict__ rp,
                            int H, int W, float coefLR, float coefDS) {
    int idx = blockIdx.x * blockDim.x + threadIdx.x;
    int total = BATCH * H * W;
    float accLR = 0.f, accDS = 0.f;
    if (idx < total) {
        int i = idx % W; int t = idx / W;
        int j = t % H;   int b = t / H;
        long hw = (long)H * W;
        const float* dlp = disp + (long)b * 2 * hw;
        const float* drp = dlp + hw;
        int o = j * W + i;
        float dl = dlp[o];
        float dr = drp[o];
        float r2l = sample_x(drp + (long)j * W, (float)i - dl * (float)(W - 1), W);
        float l2r = sample_x(dlp + (long)j * W, (float)i + dr * (float)(W - 1), W);
        accLR = fabsf(dl - r2l) + fabsf(dr - l2r);

        const float* L = lp + (long)b * 3 * hw + o;
        const float* R = rp + (long)b * 3 * hw + o;
        const float third = 1.f / 3.f;
        if (i < W - 1) {
            float aL = fabsf(L[0] - L[1]) + fabsf(L[hw] - L[hw + 1]) + fabsf(L[2 * hw] - L[2 * hw + 1]);
            float aR = fabsf(R[0] - R[1]) + fabsf(R[hw] - R[hw + 1]) + fabsf(R[2 * hw] - R[2 * hw + 1]);
            accDS += fabsf(dl - dlp[o + 1]) * __expf(-aL * third);
            accDS += fabsf(dr - drp[o + 1]) * __expf(-aR * third);
        }
        if (j < H - 1) {
            float aL = fabsf(L[0] - L[W]) + fabsf(L[hw] - L[hw + W]) + fabsf(L[2 * hw] - L[2 * hw + W]);
            float aR = fabsf(R[0] - R[W]) + fabsf(R[hw] - R[hw + W]) + fabsf(R[2 * hw] - R[2 * hw + W]);
            accDS += fabsf(dl - dlp[o + W]) * __expf(-aL * third);
            accDS += fabsf(dr - drp[o + W]) * __expf(-aR * third);
        }
    }
    float s1 = blockReduce(accLR);
    if (threadIdx.x == 0) atomicAdd(&g_acc[1], (double)(coefLR * s1));
    __syncthreads();
    float s2 = blockReduce(accDS);
    if (threadIdx.x == 0) atomicAdd(&g_acc[2], (double)(coefDS * s2));
}

__global__ void finalize_kernel(float* __restrict__ out) {
    float AP = (float)g_acc[0];
    float LR = (float)g_acc[1];
    float DS = (float)g_acc[2];
    out[0] = AP + LR + DS;
    out[1] = AP;
    out[2] = LR;
    out[3] = DS;
}

// -------------------- host --------------------
extern "C" void kernel_launch(void* const* d_in, const int* in_sizes, int n_in,
                              void* d_out, int out_size) {
    const float* disp[4];
    for (int i = 0; i < 4; i++) disp[i] = (const float*)d_in[i];
    const float* left = (const float*)d_in[4];
    const float* right = (const float*)d_in[5];

    float *pl, *pr;
    cudaGetSymbolAddress((void**)&pl, g_pyr_l);
    cudaGetSymbolAddress((void**)&pr, g_pyr_r);

    const int H = 256, W = 512;
    const int TB = 256;

    zero_acc_kernel<<<1, 32>>>();

    const float* lp[4];
    const float* rp[4];
    lp[0] = left; rp[0] = right;
    float* lbuf[4] = {nullptr, pl + OFF_L1, pl + OFF_L2, pl + OFF_L3};
    float* rbuf[4] = {nullptr, pr + OFF_L1, pr + OFF_L2, pr + OFF_L3};

    for (int i = 1; i < 4; i++) {
        int hin = H >> (i - 1), win = W >> (i - 1);
        int ho = H >> i, wo = W >> i;
        int tot = BATCH * 3 * ho * wo;
        int grid = (tot + TB - 1) / TB;
        resize_kernel<<<grid, TB>>>(lp[i - 1], lbuf[i], 3, hin, win, ho, wo);
        resize_kernel<<<grid, TB>>>(rp[i - 1], rbuf[i], 3, hin, win, ho, wo);
        lp[i] = lbuf[i];
        rp[i] = rbuf[i];
    }

    for (int i = 0; i < 4; i++) {
        int h = H >> i, w = W >> i;
        int totI = BATCH * 3 * h * w;
        int totD = BATCH * h * w;
        int gD = (totD + TB - 1) / TB;

        float coefS = (A_AP * A_AP) / ((float)BATCH * 3.f * (float)(h - 2) * (float)(w - 2));
        float coefL = (A_AP * (1.f - A_AP)) / (float)totI;

        dim3 blk(BX, BY);
        dim3 grd((w + BX - 1) / BX, (h + BY - 1) / BY, BATCH);

        // left_est = warp(rp, -dl); AP term vs lp
        fused_ap_kernel<<<grd, blk>>>(lp[i], rp[i], disp[i], 0, -1.f, h, w, coefS, coefL);
        // right_est = warp(lp, +dr); AP term vs rp
        fused_ap_kernel<<<grd, blk>>>(rp[i], lp[i], disp[i], h * w, +1.f, h, w, coefS, coefL);

        lrds_kernel<<<gD, TB>>>(disp[i], lp[i], rp[i], h, w,
                                1.0f / (float)totD,
                                A_DS / ((float)totD * (float)(1 << i)));
    }

    finalize_kernel<<<1, 1>>>((float*)d_out);
}

// round 4
// speedup vs baseline: 1.3966x; 1.2806x over previous
#include <cuda_runtime.h>
#include <math.h>

#define BATCH 32
#define A_AP 0.85f
#define A_DS 0.1f
#define CC1 (0.01f * 0.01f)
#define CC2 (0.03f * 0.03f)

// ---- static device scratch (no allocs allowed) ----
#define OFF_L1 0
#define OFF_L2 3145728
#define OFF_L3 3932160
#define PYR_TOT 4128768
__device__ float g_pyr_l[PYR_TOT];
__device__ float g_pyr_r[PYR_TOT];
// accumulators: AP, LR, DS
__device__ double g_acc[3];

// -------------------- helpers --------------------
__device__ __forceinline__ float blockReduce(float v) {
    __shared__ float sh[32];
    int tid = threadIdx.y * blockDim.x + threadIdx.x;
    int lane = tid & 31;
    int wid = tid >> 5;
    #pragma unroll
    for (int o = 16; o; o >>= 1) v += __shfl_down_sync(0xffffffffu, v, o);
    if (lane == 0) sh[wid] = v;
    __syncthreads();
    int nw = (blockDim.x * blockDim.y + 31) >> 5;
    v = (tid < nw) ? sh[tid] : 0.0f;
    if (wid == 0) {
        #pragma unroll
        for (int o = 16; o; o >>= 1) v += __shfl_down_sync(0xffffffffu, v, o);
    }
    return v;
}

__global__ void zero_acc_kernel() {
    if (threadIdx.x < 3) g_acc[threadIdx.x] = 0.0;
}

// bilinear align_corners resize, both sides in one launch (b in [0,2*BATCH))
__global__ void resize_kernel(const float* __restrict__ inL, const float* __restrict__ inR,
                              float* __restrict__ outL, float* __restrict__ outR,
                              int Hin, int Win, int Hout, int Wout) {
    int idx = blockIdx.x * blockDim.x + threadIdx.x;
    int total = 2 * BATCH * 3 * Hout * Wout;
    if (idx >= total) return;
    int i = idx % Wout; int t = idx / Wout;
    int j = t % Hout;   t /= Hout;
    int c = t % 3;      int b2 = t / 3;
    int side = (b2 >= BATCH);
    int b = b2 - side * BATCH;
    const float* in = side ? inR : inL;
    float* out = side ? outR : outL;

    float sy = (float)(Hin - 1) / (float)(Hout - 1);
    float sx = (float)(Win - 1) / (float)(Wout - 1);
    float y = j * sy, x = i * sx;
    int y0 = (int)floorf(y);
    int y1 = min(y0 + 1, Hin - 1);
    int x0 = (int)floorf(x);
    int x1 = min(x0 + 1, Win - 1);
    float wy = y - (float)y0;
    float wx = x - (float)x0;
    const float* p = in + ((long)(b * 3 + c) * Hin) * Win;
    float tl = p[y0 * Win + x0], tr = p[y0 * Win + x1];
    float bl = p[y1 * Win + x0], br = p[y1 * Win + x1];
    float top = tl * (1.f - wy) + bl * wy;
    float bot = tr * (1.f - wy) + br * wy;
    out[((long)(b * 3 + c) * Hout + j) * Wout + i] = top * (1.f - wx) + bot * wx;
}

// 1-D bilinear gather from a shared row, zero padding outside [0,W-1]
__device__ __forceinline__ float sample_sh(const float* __restrict__ row, float x, int W) {
    float x0f = floorf(x);
    int x0 = (int)x0f;
    float w1 = x - x0f;
    float v = 0.f;
    if (x0 >= 0 && x0 < W) v += row[x0] * (1.f - w1);
    int x1 = x0 + 1;
    if (x1 >= 0 && x1 < W) v += row[x1] * w1;
    return v;
}

// global-memory variant (for lrds)
__device__ __forceinline__ float sample_x(const float* __restrict__ row, float x, int W) {
    float x0f = floorf(x);
    int x0 = (int)x0f;
    float w1 = x - x0f;
    float v = 0.f;
    if (x0 >= 0 && x0 < W) v += __ldg(row + x0) * (1.f - w1);
    int x1 = x0 + 1;
    if (x1 >= 0 && x1 < W) v += __ldg(row + x1) * w1;
    return v;
}

// ---- merged AP kernel: both stereo directions, row-sliding separable SSIM ----
// block: W threads; blockIdx.x = strip, blockIdx.y = batch
__global__ void ap_kernel(const float* __restrict__ lp, const float* __restrict__ rp,
                          const float* __restrict__ disp,
                          int H, int W, int S, float coefS, float coefL) {
    __shared__ float Ls[512], Rs[512], El[512], Er[512];

    int i = threadIdx.x;
    int b = blockIdx.y;
    int r0 = blockIdx.x * S;
    long hw = (long)H * W;
    const float* dlp = disp + (long)b * 2 * hw;
    const float* drp = dlp + hw;
    float Wm1 = (float)(W - 1);
    const float inv9 = 1.f / 9.f;

    float acc = 0.f;

    #pragma unroll 1
    for (int c = 0; c < 3; c++) {
        const float* L = lp + (long)(b * 3 + c) * hw;
        const float* R = rp + (long)(b * 3 + c) * hw;

        // 3-row ring of horizontal sums: [0]=oldest. 5 sums x 2 sides.
        float lX[3] = {0,0,0}, lY[3] = {0,0,0}, lXX[3] = {0,0,0}, lYY[3] = {0,0,0}, lXY[3] = {0,0,0};
        float rX[3] = {0,0,0}, rY[3] = {0,0,0}, rXX[3] = {0,0,0}, rYY[3] = {0,0,0}, rXY[3] = {0,0,0};

        for (int j = r0 - 1; j <= r0 + S; j++) {
            bool inRow = (j >= 0 && j < H);
            __syncthreads();   // protect prior h-sum reads before overwrite
            float dlv = 0.f, drv = 0.f, xl = 0.f, xr = 0.f;
            if (inRow) {
                long o = (long)j * W + i;
                dlv = dlp[o]; drv = drp[o];
                xl = L[o]; xr = R[o];
                Ls[i] = xl; Rs[i] = xr;
            }
            __syncthreads();
            float el = 0.f, er = 0.f;
            if (inRow) {
                el = sample_sh(Rs, (float)i - dlv * Wm1, W);
                er = sample_sh(Ls, (float)i + drv * Wm1, W);
                El[i] = el; Er[i] = er;
            }
            if (inRow && j >= r0 && j < r0 + S)
                acc += coefL * (fabsf(xl - el) + fabsf(xr - er));
            __syncthreads();

            // horizontal 3-sums (only meaningful at i in [1,W-2])
            float hX_l = 0, hY_l = 0, hXX_l = 0, hYY_l = 0, hXY_l = 0;
            float hX_r = 0, hY_r = 0, hXX_r = 0, hYY_r = 0, hXY_r = 0;
            if (inRow && i >= 1 && i <= W - 2) {
                float x0 = Ls[i - 1], x1 = Ls[i], x2 = Ls[i + 1];
                float y0 = El[i - 1], y1 = El[i], y2 = El[i + 1];
                hX_l = x0 + x1 + x2;
                hY_l = y0 + y1 + y2;
                hXX_l = x0 * x0 + x1 * x1 + x2 * x2;
                hYY_l = y0 * y0 + y1 * y1 + y2 * y2;
                hXY_l = x0 * y0 + x1 * y1 + x2 * y2;
                float u0 = Rs[i - 1], u1 = Rs[i], u2 = Rs[i + 1];
                float v0 = Er[i - 1], v1 = Er[i], v2 = Er[i + 1];
                hX_r = u0 + u1 + u2;
                hY_r = v0 + v1 + v2;
                hXX_r = u0 * u0 + u1 * u1 + u2 * u2;
                hYY_r = v0 * v0 + v1 * v1 + v2 * v2;
                hXY_r = u0 * v0 + u1 * v1 + u2 * v2;
            }

            // emit SSIM for center row cj = j-1 (needs rows j-2, j-1, j)
            int cj = j - 1;
            if (cj >= r0 && cj < r0 + S && cj >= 1 && cj <= H - 2 && i >= 1 && i <= W - 2) {
                // left side
                {
                    float sx = lX[1] + lX[2] + hX_l;
                    float sy = lY[1] + lY[2] + hY_l;
                    float sxx = lXX[1] + lXX[2] + hXX_l;
                    float syy = lYY[1] + lYY[2] + hYY_l;
                    float sxy = lXY[1] + lXY[2] + hXY_l;
                    float mux = sx * inv9, muy = sy * inv9;
                    float sigx = sxx * inv9 - mux * mux;
                    float sigy = syy * inv9 - muy * muy;
                    float cov  = sxy * inv9 - mux * muy;
                    float ssim = ((2.f * mux * muy + CC1) * (2.f * cov + CC2)) /
                                 ((mux * mux + muy * muy + CC1) * (sigx + sigy + CC2));
                    float v = fminf(fmaxf((1.f - ssim) * 0.5f, 0.f), 1.f);
                    acc += coefS * v;
                }
                // right side
                {
                    float sx = rX[1] + rX[2] + hX_r;
                    float sy = rY[1] + rY[2] + hY_r;
                    float sxx = rXX[1] + rXX[2] + hXX_r;
                    float syy = rYY[1] + rYY[2] + hYY_r;
                    float sxy = rXY[1] + rXY[2] + hXY_r;
                    float mux = sx * inv9, muy = sy * inv9;
                    float sigx = sxx * inv9 - mux * mux;
                    float sigy = syy * inv9 - muy * muy;
                    float cov  = sxy * inv9 - mux * muy;
                    float ssim = ((2.f * mux * muy + CC1) * (2.f * cov + CC2)) /
                                 ((mux * mux + muy * muy + CC1) * (sigx + sigy + CC2));
                    float v = fminf(fmaxf((1.f - ssim) * 0.5f, 0.f), 1.f);
                    acc += coefS * v;
                }
            }

            // rotate ring
            lX[0]=lX[1]; lX[1]=lX[2]; lX[2]=hX_l;
            lY[0]=lY[1]; lY[1]=lY[2]; lY[2]=hY_l;
            lXX[0]=lXX[1]; lXX[1]=lXX[2]; lXX[2]=hXX_l;
            lYY[0]=lYY[1]; lYY[1]=lYY[2]; lYY[2]=hYY_l;
            lXY[0]=lXY[1]; lXY[1]=lXY[2]; lXY[2]=hXY_l;
            rX[0]=rX[1]; rX[1]=rX[2]; rX[2]=hX_r;
            rY[0]=rY[1]; rY[1]=rY[2]; rY[2]=hY_r;
            rXX[0]=rXX[1]; rXX[1]=rXX[2]; rXX[2]=hXX_r;
            rYY[0]=rYY[1]; rYY[1]=rYY[2]; rYY[2]=hYY_r;
            rXY[0]=rXY[1]; rXY[1]=rXY[2]; rXY[2]=hXY_r;
        }
    }

    float s = blockReduce(acc);
    if (i == 0 && threadIdx.y == 0) atomicAdd(&g_acc[0], (double)s);
}

// ---- fused LR consistency + edge-aware smoothness ----
__global__ void lrds_kernel(const float* __restrict__ disp,
                            const float* __restrict__ lp, const float* __restrict__ rp,
                            int H, int W, float coefLR, float coefDS) {
    int idx = blockIdx.x * blockDim.x + threadIdx.x;
    int total = BATCH * H * W;
    float accLR = 0.f, accDS = 0.f;
    if (idx < total) {
        int i = idx % W; int t = idx / W;
        int j = t % H;   int b = t / H;
        long hw = (long)H * W;
        const float* dlp = disp + (long)b * 2 * hw;
        const float* drp = dlp + hw;
        int o = j * W + i;
        float dl = dlp[o];
        float dr = drp[o];
        float r2l = sample_x(drp + (long)j * W, (float)i - dl * (float)(W - 1), W);
        float l2r = sample_x(dlp + (long)j * W, (float)i + dr * (float)(W - 1), W);
        accLR = fabsf(dl - r2l) + fabsf(dr - l2r);

        const float* L = lp + (long)b * 3 * hw + o;
        const float* R = rp + (long)b * 3 * hw + o;
        const float third = 1.f / 3.f;
        if (i < W - 1) {
            float aL = fabsf(L[0] - L[1]) + fabsf(L[hw] - L[hw + 1]) + fabsf(L[2 * hw] - L[2 * hw + 1]);
            float aR = fabsf(R[0] - R[1]) + fabsf(R[hw] - R[hw + 1]) + fabsf(R[2 * hw] - R[2 * hw + 1]);
            accDS += fabsf(dl - dlp[o + 1]) * __expf(-aL * third);
            accDS += fabsf(dr - drp[o + 1]) * __expf(-aR * third);
        }
        if (j < H - 1) {
            float aL = fabsf(L[0] - L[W]) + fabsf(L[hw] - L[hw + W]) + fabsf(L[2 * hw] - L[2 * hw + W]);
            float aR = fabsf(R[0] - R[W]) + fabsf(R[hw] - R[hw + W]) + fabsf(R[2 * hw] - R[2 * hw + W]);
            accDS += fabsf(dl - dlp[o + W]) * __expf(-aL * third);
            accDS += fabsf(dr - drp[o + W]) * __expf(-aR * third);
        }
    }
    float s1 = blockReduce(accLR);
    if (threadIdx.x == 0) atomicAdd(&g_acc[1], (double)(coefLR * s1));
    __syncthreads();
    float s2 = blockReduce(accDS);
    if (threadIdx.x == 0) atomicAdd(&g_acc[2], (double)(coefDS * s2));
}

__global__ void finalize_kernel(float* __restrict__ out) {
    float AP = (float)g_acc[0];
    float LR = (float)g_acc[1];
    float DS = (float)g_acc[2];
    out[0] = AP + LR + DS;
    out[1] = AP;
    out[2] = LR;
    out[3] = DS;
}

// -------------------- host --------------------
extern "C" void kernel_launch(void* const* d_in, const int* in_sizes, int n_in,
                              void* d_out, int out_size) {
    const float* disp[4];
    for (int i = 0; i < 4; i++) disp[i] = (const float*)d_in[i];
    const float* left = (const float*)d_in[4];
    const float* right = (const float*)d_in[5];

    float *pl, *pr;
    cudaGetSymbolAddress((void**)&pl, g_pyr_l);
    cudaGetSymbolAddress((void**)&pr, g_pyr_r);

    const int H = 256, W = 512;
    const int TB = 256;

    zero_acc_kernel<<<1, 32>>>();

    const float* lp[4];
    const float* rp[4];
    lp[0] = left; rp[0] = right;
    float* lbuf[4] = {nullptr, pl + OFF_L1, pl + OFF_L2, pl + OFF_L3};
    float* rbuf[4] = {nullptr, pr + OFF_L1, pr + OFF_L2, pr + OFF_L3};

    for (int i = 1; i < 4; i++) {
        int hin = H >> (i - 1), win = W >> (i - 1);
        int ho = H >> i, wo = W >> i;
        int tot = 2 * BATCH * 3 * ho * wo;
        int grid = (tot + TB - 1) / TB;
        resize_kernel<<<grid, TB>>>(lp[i - 1], rp[i - 1], lbuf[i], rbuf[i], hin, win, ho, wo);
        lp[i] = lbuf[i];
        rp[i] = rbuf[i];
    }

    const int Svals[4] = {16, 16, 16, 8};

    for (int i = 0; i < 4; i++) {
        int h = H >> i, w = W >> i;
        int totI = BATCH * 3 * h * w;
        int totD = BATCH * h * w;
        int gD = (totD + TB - 1) / TB;

        float coefS = (A_AP * A_AP) / ((float)BATCH * 3.f * (float)(h - 2) * (float)(w - 2));
        float coefL = (A_AP * (1.f - A_AP)) / (float)totI;

        int S = Svals[i];
        dim3 grd(h / S, BATCH);
        ap_kernel<<<grd, w>>>(lp[i], rp[i], disp[i], h, w, S, coefS, coefL);

        lrds_kernel<<<gD, TB>>>(disp[i], lp[i], rp[i], h, w,
                                1.0f / (float)totD,
                                A_DS / ((float)totD * (float)(1 << i)));
    }

    finalize_kernel<<<1, 1>>>((float*)d_out);
}

// round 5
// speedup vs baseline: 1.5453x; 1.1065x over previous
#include <cuda_runtime.h>
#include <math.h>

#define BATCH 32
#define A_AP 0.85f
#define A_DS 0.1f
#define CC1 (0.01f * 0.01f)
#define CC2 (0.03f * 0.03f)
#define NT 256
#define APR 6            // output rows per block

// ---- static device scratch (no allocs allowed) ----
#define OFF_L1 0
#define OFF_L2 3145728
#define OFF_L3 3932160
#define PYR_TOT 4128768
__device__ float g_pyr_l[PYR_TOT];
__device__ float g_pyr_r[PYR_TOT];
// accumulators: AP, LR, DS
__device__ double g_acc[3];

// -------------------- helpers --------------------
__device__ __forceinline__ float blockReduce(float v) {
    __shared__ float sh[32];
    int tid = threadIdx.y * blockDim.x + threadIdx.x;
    int lane = tid & 31;
    int wid = tid >> 5;
    #pragma unroll
    for (int o = 16; o; o >>= 1) v += __shfl_down_sync(0xffffffffu, v, o);
    if (lane == 0) sh[wid] = v;
    __syncthreads();
    int nw = (blockDim.x * blockDim.y + 31) >> 5;
    v = (tid < nw) ? sh[tid] : 0.0f;
    if (wid == 0) {
        #pragma unroll
        for (int o = 16; o; o >>= 1) v += __shfl_down_sync(0xffffffffu, v, o);
    }
    return v;
}

__global__ void zero_acc_kernel() {
    if (threadIdx.x < 3) g_acc[threadIdx.x] = 0.0;
}

// bilinear align_corners resize, both sides in one launch
__global__ void resize_kernel(const float* __restrict__ inL, const float* __restrict__ inR,
                              float* __restrict__ outL, float* __restrict__ outR,
                              int Hin, int Win, int Hout, int Wout) {
    int idx = blockIdx.x * blockDim.x + threadIdx.x;
    int total = 2 * BATCH * 3 * Hout * Wout;
    if (idx >= total) return;
    int i = idx % Wout; int t = idx / Wout;
    int j = t % Hout;   t /= Hout;
    int c = t % 3;      int b2 = t / 3;
    int side = (b2 >= BATCH);
    int b = b2 - side * BATCH;
    const float* in = side ? inR : inL;
    float* out = side ? outR : outL;

    float sy = (float)(Hin - 1) / (float)(Hout - 1);
    float sx = (float)(Win - 1) / (float)(Wout - 1);
    float y = j * sy, x = i * sx;
    int y0 = (int)floorf(y);
    int y1 = min(y0 + 1, Hin - 1);
    int x0 = (int)floorf(x);
    int x1 = min(x0 + 1, Win - 1);
    float wy = y - (float)y0;
    float wx = x - (float)x0;
    const float* p = in + ((long)(b * 3 + c) * Hin) * Win;
    float tl = p[y0 * Win + x0], tr = p[y0 * Win + x1];
    float bl = p[y1 * Win + x0], br = p[y1 * Win + x1];
    float top = tl * (1.f - wy) + bl * wy;
    float bot = tr * (1.f - wy) + br * wy;
    out[((long)(b * 3 + c) * Hout + j) * Wout + i] = top * (1.f - wx) + bot * wx;
}

// 1-D bilinear gather from a shared row, zero padding outside [0,W-1]
__device__ __forceinline__ float sample_sh(const float* __restrict__ row, float x, int W) {
    float x0f = floorf(x);
    int x0 = (int)x0f;
    float w1 = x - x0f;
    float v = 0.f;
    if (x0 >= 0 && x0 < W) v += row[x0] * (1.f - w1);
    int x1 = x0 + 1;
    if (x1 >= 0 && x1 < W) v += row[x1] * w1;
    return v;
}

// global-memory variant (for lrds)
__device__ __forceinline__ float sample_x(const float* __restrict__ row, float x, int W) {
    float x0f = floorf(x);
    int x0 = (int)x0f;
    float w1 = x - x0f;
    float v = 0.f;
    if (x0 >= 0 && x0 < W) v += __ldg(row + x0) * (1.f - w1);
    int x1 = x0 + 1;
    if (x1 >= 0 && x1 < W) v += __ldg(row + x1) * w1;
    return v;
}

// horizontal 3-sums for both stereo sides at shared index 'base'
__device__ __forceinline__ void hsum10(const float* __restrict__ Xl, const float* __restrict__ El,
                                       const float* __restrict__ Xr, const float* __restrict__ Er,
                                       int base, float* o) {
    float x0 = Xl[base - 1], x1 = Xl[base], x2 = Xl[base + 1];
    float e0 = El[base - 1], e1 = El[base], e2 = El[base + 1];
    o[0] = x0 + x1 + x2;
    o[1] = e0 + e1 + e2;
    o[2] = x0 * x0 + x1 * x1 + x2 * x2;
    o[3] = e0 * e0 + e1 * e1 + e2 * e2;
    o[4] = x0 * e0 + x1 * e1 + x2 * e2;
    float u0 = Xr[base - 1], u1 = Xr[base], u2 = Xr[base + 1];
    float v0 = Er[base - 1], v1 = Er[base], v2 = Er[base + 1];
    o[5] = u0 + u1 + u2;
    o[6] = v0 + v1 + v2;
    o[7] = u0 * u0 + u1 * u1 + u2 * u2;
    o[8] = v0 * v0 + v1 * v1 + v2 * v2;
    o[9] = u0 * v0 + u1 * v1 + u2 * v2;
}

__device__ __forceinline__ float ssim_val(float sx, float sy, float sxx, float syy, float sxy) {
    const float inv9 = 1.f / 9.f;
    float mux = sx * inv9, muy = sy * inv9;
    float sigx = sxx * inv9 - mux * mux;
    float sigy = syy * inv9 - muy * muy;
    float cov  = sxy * inv9 - mux * muy;
    float ssim = ((2.f * mux * muy + CC1) * (2.f * cov + CC2)) /
                 ((mux * mux + muy * muy + CC1) * (sigx + sigy + CC2));
    return fminf(fmaxf((1.f - ssim) * 0.5f, 0.f), 1.f);
}

// ---- merged AP kernel: tile-staged, both stereo directions, separable SSIM ----
// block: NT threads; blockIdx.x = row strip (APR rows), blockIdx.y = batch
__global__ void ap_kernel(const float* __restrict__ lp, const float* __restrict__ rp,
                          const float* __restrict__ disp,
                          int H, int W, int Wsh, float coefS, float coefL) {
    extern __shared__ float sh[];
    const int rows = APR + 2;
    const int Wp = W + 1;          // padded row stride (bank-conflict avoidance)
    float* Xl = sh;
    float* Xr = Xl + rows * Wp;
    float* El = Xr + rows * Wp;
    float* Er = El + rows * Wp;

    int tid = threadIdx.x;
    int b = blockIdx.y;
    int r0 = blockIdx.x * APR;
    long hw = (long)H * W;
    const float* dlp = disp + (long)b * 2 * hw;
    const float* drp = dlp + hw;
    float Wm1 = (float)(W - 1);
    int total = rows * W;
    float acc = 0.f;

    #pragma unroll 1
    for (int c = 0; c < 3; c++) {
        const float* L = lp + (long)(b * 3 + c) * hw;
        const float* Rg = rp + (long)(b * 3 + c) * hw;

        // phase A: stage L and R rows (zero-pad out of image)
        for (int idx = tid; idx < total; idx += NT) {
            int r = idx >> Wsh;
            int i = idx & (W - 1);
            int gj = r0 - 1 + r;
            float xl = 0.f, xr = 0.f;
            if (gj >= 0 && gj < H) {
                long o = (long)gj * W + i;
                xl = L[o]; xr = Rg[o];
            }
            Xl[r * Wp + i] = xl;
            Xr[r * Wp + i] = xr;
        }
        __syncthreads();

        // phase B: warp estimates from shared rows + L1 term
        for (int idx = tid; idx < total; idx += NT) {
            int r = idx >> Wsh;
            int i = idx & (W - 1);
            int gj = r0 - 1 + r;
            float el = 0.f, er = 0.f;
            if (gj >= 0 && gj < H) {
                long o = (long)gj * W + i;
                float dlv = dlp[o], drv = drp[o];
                el = sample_sh(Xr + r * Wp, (float)i - dlv * Wm1, W);
                er = sample_sh(Xl + r * Wp, (float)i + drv * Wm1, W);
                if (r >= 1 && r <= APR)
                    acc += coefL * (fabsf(Xl[r * Wp + i] - el) + fabsf(Xr[r * Wp + i] - er));
            }
            El[r * Wp + i] = el;
            Er[r * Wp + i] = er;
        }
        __syncthreads();

        // phase C: separable SSIM, per-column register ring over staged rows
        {
            int Wc = (W < NT) ? W : NT;
            int groups = NT / Wc;
            int gid = tid / Wc;
            int col0 = tid - gid * Wc;
            int Rgp = (APR + groups - 1) / groups;
            int lrA = 1 + gid * Rgp;
            int lrB = min(lrA + Rgp, APR + 1);

            for (int col = col0; col < W; col += Wc) {
                if (col == 0 || col == W - 1) continue;
                if (lrA >= lrB) continue;
                float a0[10], a1[10], a2[10];
                hsum10(Xl, El, Xr, Er, (lrA - 1) * Wp + col, a0);
                hsum10(Xl, El, Xr, Er, lrA * Wp + col, a1);
                for (int lr = lrA; lr < lrB; lr++) {
                    hsum10(Xl, El, Xr, Er, (lr + 1) * Wp + col, a2);
                    int gj = r0 + lr - 1;
                    if (gj >= 1 && gj <= H - 2) {
                        float v = ssim_val(a0[0] + a1[0] + a2[0], a0[1] + a1[1] + a2[1],
                                           a0[2] + a1[2] + a2[2], a0[3] + a1[3] + a2[3],
                                           a0[4] + a1[4] + a2[4]);
                        v += ssim_val(a0[5] + a1[5] + a2[5], a0[6] + a1[6] + a2[6],
                                      a0[7] + a1[7] + a2[7], a0[8] + a1[8] + a2[8],
                                      a0[9] + a1[9] + a2[9]);
                        acc += coefS * v;
                    }
                    #pragma unroll
                    for (int k = 0; k < 10; k++) { a0[k] = a1[k]; a1[k] = a2[k]; }
                }
            }
        }
        __syncthreads();
    }

    float s = blockReduce(acc);
    if (tid == 0) atomicAdd(&g_acc[0], (double)s);
}

// ---- fused LR consistency + edge-aware smoothness ----
__global__ void lrds_kernel(const float* __restrict__ disp,
                            const float* __restrict__ lp, const float* __restrict__ rp,
                            int H, int W, float coefLR, float coefDS) {
    int idx = blockIdx.x * blockDim.x + threadIdx.x;
    int total = BATCH * H * W;
    float accLR = 0.f, accDS = 0.f;
    if (idx < total) {
        int i = idx % W; int t = idx / W;
        int j = t % H;   int b = t / H;
        long hw = (long)H * W;
        const float* dlp = disp + (long)b * 2 * hw;
        const float* drp = dlp + hw;
        int o = j * W + i;
        float dl = dlp[o];
        float dr = drp[o];
        float r2l = sample_x(drp + (long)j * W, (float)i - dl * (float)(W - 1), W);
        float l2r = sample_x(dlp + (long)j * W, (float)i + dr * (float)(W - 1), W);
        accLR = fabsf(dl - r2l) + fabsf(dr - l2r);

        const float* L = lp + (long)b * 3 * hw + o;
        const float* R = rp + (long)b * 3 * hw + o;
        const float third = 1.f / 3.f;
        if (i < W - 1) {
            float aL = fabsf(L[0] - L[1]) + fabsf(L[hw] - L[hw + 1]) + fabsf(L[2 * hw] - L[2 * hw + 1]);
            float aR = fabsf(R[0] - R[1]) + fabsf(R[hw] - R[hw + 1]) + fabsf(R[2 * hw] - R[2 * hw + 1]);
            accDS += fabsf(dl - dlp[o + 1]) * __expf(-aL * third);
            accDS += fabsf(dr - drp[o + 1]) * __expf(-aR * third);
        }
        if (j < H - 1) {
            float aL = fabsf(L[0] - L[W]) + fabsf(L[hw] - L[hw + W]) + fabsf(L[2 * hw] - L[2 * hw + W]);
            float aR = fabsf(R[0] - R[W]) + fabsf(R[hw] - R[hw + W]) + fabsf(R[2 * hw] - R[2 * hw + W]);
            accDS += fabsf(dl - dlp[o + W]) * __expf(-aL * third);
            accDS += fabsf(dr - drp[o + W]) * __expf(-aR * third);
        }
    }
    float s1 = blockReduce(accLR);
    if (threadIdx.x == 0) atomicAdd(&g_acc[1], (double)(coefLR * s1));
    __syncthreads();
    float s2 = blockReduce(accDS);
    if (threadIdx.x == 0) atomicAdd(&g_acc[2], (double)(coefDS * s2));
}

__global__ void finalize_kernel(float* __restrict__ out) {
    float AP = (float)g_acc[0];
    float LR = (float)g_acc[1];
    float DS = (float)g_acc[2];
    out[0] = AP + LR + DS;
    out[1] = AP;
    out[2] = LR;
    out[3] = DS;
}

// -------------------- host --------------------
extern "C" void kernel_launch(void* const* d_in, const int* in_sizes, int n_in,
                              void* d_out, int out_size) {
    const float* disp[4];
    for (int i = 0; i < 4; i++) disp[i] = (const float*)d_in[i];
    const float* left = (const float*)d_in[4];
    const float* right = (const float*)d_in[5];

    float *pl, *pr;
    cudaGetSymbolAddress((void**)&pl, g_pyr_l);
    cudaGetSymbolAddress((void**)&pr, g_pyr_r);

    const int H = 256, W = 512;
    const int TB = 256;

    // allow >48KB dynamic smem for ap_kernel (idempotent)
    cudaFuncSetAttribute(ap_kernel, cudaFuncAttributeMaxDynamicSharedMemorySize, 72 * 1024);

    zero_acc_kernel<<<1, 32>>>();

    const float* lp[4];
    const float* rp[4];
    lp[0] = left; rp[0] = right;
    float* lbuf[4] = {nullptr, pl + OFF_L1, pl + OFF_L2, pl + OFF_L3};
    float* rbuf[4] = {nullptr, pr + OFF_L1, pr + OFF_L2, pr + OFF_L3};

    for (int i = 1; i < 4; i++) {
        int hin = H >> (i - 1), win = W >> (i - 1);
        int ho = H >> i, wo = W >> i;
        int tot = 2 * BATCH * 3 * ho * wo;
        int grid = (tot + TB - 1) / TB;
        resize_kernel<<<grid, TB>>>(lp[i - 1], rp[i - 1], lbuf[i], rbuf[i], hin, win, ho, wo);
        lp[i] = lbuf[i];
        rp[i] = rbuf[i];
    }

    for (int i = 0; i < 4; i++) {
        int h = H >> i, w = W >> i;
        int totI = BATCH * 3 * h * w;
        int totD = BATCH * h * w;
        int gD = (totD + TB - 1) / TB;

        float coefS = (A_AP * A_AP) / ((float)BATCH * 3.f * (float)(h - 2) * (float)(w - 2));
        float coefL = (A_AP * (1.f - A_AP)) / (float)totI;

        int Wsh = (i == 0) ? 9 : (i == 1) ? 8 : (i == 2) ? 7 : 6;
        int strips = (h + APR - 1) / APR;
        size_t smem = (size_t)4 * (APR + 2) * (w + 1) * sizeof(float);
        dim3 grd(strips, BATCH);
        ap_kernel<<<grd, NT, smem>>>(lp[i], rp[i], disp[i], h, w, Wsh, coefS, coefL);

        lrds_kernel<<<gD, TB>>>(disp[i], lp[i], rp[i], h, w,
                                1.0f / (float)totD,
                                A_DS / ((float)totD * (float)(1 << i)));
    }

    finalize_kernel<<<1, 1>>>((float*)d_out);
}

// round 6
// speedup vs baseline: 1.8873x; 1.2213x over previous
#include <cuda_runtime.h>
#include <math.h>

#define BATCH 32
#define A_AP 0.85f
#define A_DS 0.1f
#define CC1 (0.01f * 0.01f)
#define CC2 (0.03f * 0.03f)
#define NT 512

// ---- static device scratch (no allocs allowed) ----
#define OFF_L1 0
#define OFF_L2 3145728
#define OFF_L3 3932160
#define PYR_TOT 4128768
__device__ float g_pyr_l[PYR_TOT];
__device__ float g_pyr_r[PYR_TOT];
// accumulators: AP, LR, DS
__device__ double g_acc[3];

// -------------------- helpers --------------------
__device__ __forceinline__ float blockReduce(float v) {
    __shared__ float sh[32];
    int tid = threadIdx.x;
    int lane = tid & 31;
    int wid = tid >> 5;
    #pragma unroll
    for (int o = 16; o; o >>= 1) v += __shfl_down_sync(0xffffffffu, v, o);
    if (lane == 0) sh[wid] = v;
    __syncthreads();
    int nw = blockDim.x >> 5;
    v = (tid < nw) ? sh[tid] : 0.0f;
    if (wid == 0) {
        #pragma unroll
        for (int o = 16; o; o >>= 1) v += __shfl_down_sync(0xffffffffu, v, o);
    }
    return v;
}

__global__ void zero_acc_kernel() {
    if (threadIdx.x < 3) g_acc[threadIdx.x] = 0.0;
}

// bilinear align_corners resize, both sides in one launch
__global__ void resize_kernel(const float* __restrict__ inL, const float* __restrict__ inR,
                              float* __restrict__ outL, float* __restrict__ outR,
                              int Hin, int Win, int Hout, int Wout) {
    int idx = blockIdx.x * blockDim.x + threadIdx.x;
    int total = 2 * BATCH * 3 * Hout * Wout;
    if (idx >= total) return;
    int i = idx % Wout; int t = idx / Wout;
    int j = t % Hout;   t /= Hout;
    int c = t % 3;      int b2 = t / 3;
    int side = (b2 >= BATCH);
    int b = b2 - side * BATCH;
    const float* in = side ? inR : inL;
    float* out = side ? outR : outL;

    float sy = (float)(Hin - 1) / (float)(Hout - 1);
    float sx = (float)(Win - 1) / (float)(Wout - 1);
    float y = j * sy, x = i * sx;
    int y0 = (int)floorf(y);
    int y1 = min(y0 + 1, Hin - 1);
    int x0 = (int)floorf(x);
    int x1 = min(x0 + 1, Win - 1);
    float wy = y - (float)y0;
    float wx = x - (float)x0;
    const float* p = in + ((long)(b * 3 + c) * Hin) * Win;
    float tl = p[y0 * Win + x0], tr = p[y0 * Win + x1];
    float bl = p[y1 * Win + x0], br = p[y1 * Win + x1];
    float top = tl * (1.f - wy) + bl * wy;
    float bot = tr * (1.f - wy) + br * wy;
    out[((long)(b * 3 + c) * Hout + j) * Wout + i] = top * (1.f - wx) + bot * wx;
}

// 1-D bilinear gather from a shared row, zero padding outside [0,W-1]
__device__ __forceinline__ float sample_sh(const float* __restrict__ row, float x, int W) {
    float x0f = floorf(x);
    int x0 = (int)x0f;
    float w1 = x - x0f;
    float v = 0.f;
    if (x0 >= 0 && x0 < W) v += row[x0] * (1.f - w1);
    int x1 = x0 + 1;
    if (x1 >= 0 && x1 < W) v += row[x1] * w1;
    return v;
}

// horizontal 3-sums for both stereo sides at shared index 'base'
__device__ __forceinline__ void hsum10(const float* __restrict__ Xl, const float* __restrict__ El,
                                       const float* __restrict__ Xr, const float* __restrict__ Er,
                                       int base, float* o) {
    float x0 = Xl[base - 1], x1 = Xl[base], x2 = Xl[base + 1];
    float e0 = El[base - 1], e1 = El[base], e2 = El[base + 1];
    o[0] = x0 + x1 + x2;
    o[1] = e0 + e1 + e2;
    o[2] = x0 * x0 + x1 * x1 + x2 * x2;
    o[3] = e0 * e0 + e1 * e1 + e2 * e2;
    o[4] = x0 * e0 + x1 * e1 + x2 * e2;
    float u0 = Xr[base - 1], u1 = Xr[base], u2 = Xr[base + 1];
    float v0 = Er[base - 1], v1 = Er[base], v2 = Er[base + 1];
    o[5] = u0 + u1 + u2;
    o[6] = v0 + v1 + v2;
    o[7] = u0 * u0 + u1 * u1 + u2 * u2;
    o[8] = v0 * v0 + v1 * v1 + v2 * v2;
    o[9] = u0 * v0 + u1 * v1 + u2 * v2;
}

__device__ __forceinline__ float ssim_val(float sx, float sy, float sxx, float syy, float sxy) {
    const float inv9 = 1.f / 9.f;
    float mux = sx * inv9, muy = sy * inv9;
    float sigx = sxx * inv9 - mux * mux;
    float sigy = syy * inv9 - muy * muy;
    float cov  = sxy * inv9 - mux * muy;
    float ssim = ((2.f * mux * muy + CC1) * (2.f * cov + CC2)) /
                 ((mux * mux + muy * muy + CC1) * (sigx + sigy + CC2));
    return fminf(fmaxf((1.f - ssim) * 0.5f, 0.f), 1.f);
}

// ---- fully fused per-level kernel: AP (warp+SSIM+L1) + LR + DS ----
// shared arrays (each rows*W): Dl, Dr, El, Er, Xl0..2, Xr0..2
__global__ __launch_bounds__(NT, 2)
void fused_kernel(const float* __restrict__ lp, const float* __restrict__ rp,
                  const float* __restrict__ disp,
                  int H, int W, int lw, int APR,
                  float coefS, float coefL, float coefLR, float coefDS) {
    extern __shared__ float sh[];
    int rows = APR + 2;
    int stride = rows * W;
    float* Dl = sh;
    float* Dr = Dl + stride;
    float* El = Dr + stride;
    float* Er = El + stride;
    float* Xs = Er + stride;   // 6 planes: Xl_c = Xs + c*stride, Xr_c = Xs + (3+c)*stride

    int tid = threadIdx.x;
    int col = tid & (W - 1);
    int rg = tid >> lw;
    int G = NT >> lw;
    int b = blockIdx.y;
    int r0 = blockIdx.x * APR;
    long hw = (long)H * W;
    const float* dlg = disp + (long)b * 2 * hw;
    const float* drg = dlg + hw;
    float Wm1 = (float)(W - 1);

    // ---- phase A: stage disp + 6 image planes (zero-pad outside image) ----
    for (int r = rg; r < rows; r += G) {
        int gj = r0 - 1 + r;
        bool in = (gj >= 0 && gj < H);
        long o = (long)gj * W + col;
        int so = r * W + col;
        Dl[so] = in ? dlg[o] : 0.f;
        Dr[so] = in ? drg[o] : 0.f;
        #pragma unroll
        for (int c = 0; c < 3; c++) {
            Xs[c * stride + so]       = in ? lp[(long)(b * 3 + c) * hw + o] : 0.f;
            Xs[(3 + c) * stride + so] = in ? rp[(long)(b * 3 + c) * hw + o] : 0.f;
        }
    }
    __syncthreads();

    float accAP = 0.f;
    #pragma unroll 1
    for (int c = 0; c < 3; c++) {
        const float* Xl = Xs + c * stride;
        const float* Xr = Xs + (3 + c) * stride;

        // ---- phase B: warp estimates from shared + L1 term ----
        for (int r = rg; r < rows; r += G) {
            int gj = r0 - 1 + r;
            int so = r * W + col;
            float el = 0.f, er = 0.f;
            if (gj >= 0 && gj < H) {
                float dlv = Dl[so], drv = Dr[so];
                el = sample_sh(Xr + r * W, (float)col - dlv * Wm1, W);
                er = sample_sh(Xl + r * W, (float)col + drv * Wm1, W);
                if (r >= 1 && r <= APR)
                    accAP += coefL * (fabsf(Xl[so] - el) + fabsf(Xr[so] - er));
            }
            El[so] = el;
            Er[so] = er;
        }
        __syncthreads();

        // ---- phase C: separable SSIM ----
        if (col >= 1 && col <= W - 2) {
            if (G == 1) {
                // register ring over rows (level 0)
                float a0[10], a1[10], a2[10];
                hsum10(Xl, El, Xr, Er, col, a0);
                hsum10(Xl, El, Xr, Er, W + col, a1);
                for (int r = 1; r <= APR; r++) {
                    hsum10(Xl, El, Xr, Er, (r + 1) * W + col, a2);
                    int gj = r0 + r - 1;
                    if (gj >= 1 && gj <= H - 2) {
                        float v = ssim_val(a0[0] + a1[0] + a2[0], a0[1] + a1[1] + a2[1],
                                           a0[2] + a1[2] + a2[2], a0[3] + a1[3] + a2[3],
                                           a0[4] + a1[4] + a2[4]);
                        v += ssim_val(a0[5] + a1[5] + a2[5], a0[6] + a1[6] + a2[6],
                                      a0[7] + a1[7] + a2[7], a0[8] + a1[8] + a2[8],
                                      a0[9] + a1[9] + a2[9]);
                        accAP += coefS * v;
                    }
                    #pragma unroll
                    for (int k = 0; k < 10; k++) { a0[k] = a1[k]; a1[k] = a2[k]; }
                }
            } else {
                for (int r = 1 + rg; r <= APR; r += G) {
                    int gj = r0 + r - 1;
                    if (gj >= 1 && gj <= H - 2) {
                        float a0[10], a1[10], a2[10];
                        hsum10(Xl, El, Xr, Er, (r - 1) * W + col, a0);
                        hsum10(Xl, El, Xr, Er, r * W + col, a1);
                        hsum10(Xl, El, Xr, Er, (r + 1) * W + col, a2);
                        float v = ssim_val(a0[0] + a1[0] + a2[0], a0[1] + a1[1] + a2[1],
                                           a0[2] + a1[2] + a2[2], a0[3] + a1[3] + a2[3],
                                           a0[4] + a1[4] + a2[4]);
                        v += ssim_val(a0[5] + a1[5] + a2[5], a0[6] + a1[6] + a2[6],
                                      a0[7] + a1[7] + a2[7], a0[8] + a1[8] + a2[8],
                                      a0[9] + a1[9] + a2[9]);
                        accAP += coefS * v;
                    }
                }
            }
        }
        __syncthreads();
    }

    // ---- phase D: LR consistency + edge-aware smoothness (all from shared) ----
    float accLR = 0.f, accDS = 0.f;
    const float third = 1.f / 3.f;
    for (int r = 1 + rg; r <= APR; r += G) {
        int gj = r0 + r - 1;
        if (gj >= H) continue;
        int so = r * W + col;
        float dlv = Dl[so], drv = Dr[so];
        float r2l = sample_sh(Dr + r * W, (float)col - dlv * Wm1, W);
        float l2r = sample_sh(Dl + r * W, (float)col + drv * Wm1, W);
        accLR += fabsf(dlv - r2l) + fabsf(drv - l2r);

        if (col < W - 1) {
            float aL = 0.f, aR = 0.f;
            #pragma unroll
            for (int c = 0; c < 3; c++) {
                aL += fabsf(Xs[c * stride + so] - Xs[c * stride + so + 1]);
                aR += fabsf(Xs[(3 + c) * stride + so] - Xs[(3 + c) * stride + so + 1]);
            }
            accDS += fabsf(dlv - Dl[so + 1]) * __expf(-aL * third)
                   + fabsf(drv - Dr[so + 1]) * __expf(-aR * third);
        }
        if (gj < H - 1) {
            float aL = 0.f, aR = 0.f;
            #pragma unroll
            for (int c = 0; c < 3; c++) {
                aL += fabsf(Xs[c * stride + so] - Xs[c * stride + so + W]);
                aR += fabsf(Xs[(3 + c) * stride + so] - Xs[(3 + c) * stride + so + W]);
            }
            accDS += fabsf(dlv - Dl[so + W]) * __expf(-aL * third)
                   + fabsf(drv - Dr[so + W]) * __expf(-aR * third);
        }
    }

    float s0 = blockReduce(accAP);
    if (tid == 0) atomicAdd(&g_acc[0], (double)s0);
    __syncthreads();
    float s1 = blockReduce(accLR);
    if (tid == 0) atomicAdd(&g_acc[1], (double)(coefLR * s1));
    __syncthreads();
    float s2 = blockReduce(accDS);
    if (tid == 0) atomicAdd(&g_acc[2], (double)(coefDS * s2));
}

__global__ void finalize_kernel(float* __restrict__ out) {
    float AP = (float)g_acc[0];
    float LR = (float)g_acc[1];
    float DS = (float)g_acc[2];
    out[0] = AP + LR + DS;
    out[1] = AP;
    out[2] = LR;
    out[3] = DS;
}

// -------------------- host --------------------
extern "C" void kernel_launch(void* const* d_in, const int* in_sizes, int n_in,
                              void* d_out, int out_size) {
    const float* disp[4];
    for (int i = 0; i < 4; i++) disp[i] = (const float*)d_in[i];
    const float* left = (const float*)d_in[4];
    const float* right = (const float*)d_in[5];

    float *pl, *pr;
    cudaGetSymbolAddress((void**)&pl, g_pyr_l);
    cudaGetSymbolAddress((void**)&pr, g_pyr_r);

    const int H = 256, W = 512;
    const int TB = 256;

    cudaFuncSetAttribute(fused_kernel, cudaFuncAttributeMaxDynamicSharedMemorySize, 104 * 1024);

    zero_acc_kernel<<<1, 32>>>();

    const float* lp[4];
    const float* rp[4];
    lp[0] = left; rp[0] = right;
    float* lbuf[4] = {nullptr, pl + OFF_L1, pl + OFF_L2, pl + OFF_L3};
    float* rbuf[4] = {nullptr, pr + OFF_L1, pr + OFF_L2, pr + OFF_L3};

    for (int i = 1; i < 4; i++) {
        int hin = H >> (i - 1), win = W >> (i - 1);
        int ho = H >> i, wo = W >> i;
        int tot = 2 * BATCH * 3 * ho * wo;
        int grid = (tot + TB - 1) / TB;
        resize_kernel<<<grid, TB>>>(lp[i - 1], rp[i - 1], lbuf[i], rbuf[i], hin, win, ho, wo);
        lp[i] = lbuf[i];
        rp[i] = rbuf[i];
    }

    const int APRv[4] = {3, 6, 8, 16};
    const int LWv[4] = {9, 8, 7, 6};

    for (int i = 0; i < 4; i++) {
        int h = H >> i, w = W >> i;
        int totI = BATCH * 3 * h * w;
        int totD = BATCH * h * w;

        float coefS = (A_AP * A_AP) / ((float)BATCH * 3.f * (float)(h - 2) * (float)(w - 2));
        float coefL = (A_AP * (1.f - A_AP)) / (float)totI;
        float coefLR = 1.0f / (float)totD;
        float coefDS = A_DS / ((float)totD * (float)(1 << i));

        int APR = APRv[i];
        int strips = (h + APR - 1) / APR;
        size_t smem = (size_t)10 * (APR + 2) * w * sizeof(float);
        dim3 grd(strips, BATCH);
        fused_kernel<<<grd, NT, smem>>>(lp[i], rp[i], disp[i], h, w, LWv[i], APR,
                                        coefS, coefL, coefLR, coefDS);
    }

    finalize_kernel<<<1, 1>>>((float*)d_out);
}

// round 10
// speedup vs baseline: 1.9642x; 1.0407x over previous
#include <cuda_runtime.h>
#include <math.h>

#define BATCH 32
#define A_AP 0.85f
#define A_DS 0.1f
#define CC1 (0.01f * 0.01f)
#define CC2 (0.03f * 0.03f)
#define NT 512

// ---- static device scratch (no allocs allowed) ----
#define OFF_L1 0
#define OFF_L2 3145728
#define OFF_L3 3932160
#define PYR_TOT 4128768
__device__ float g_pyr_l[PYR_TOT];
__device__ float g_pyr_r[PYR_TOT];
// accumulators: AP, LR, DS
__device__ double g_acc[3];

// -------------------- helpers --------------------
__device__ __forceinline__ float blockReduce(float v) {
    __shared__ float sh[32];
    int tid = threadIdx.x;
    int lane = tid & 31;
    int wid = tid >> 5;
    #pragma unroll
    for (int o = 16; o; o >>= 1) v += __shfl_down_sync(0xffffffffu, v, o);
    if (lane == 0) sh[wid] = v;
    __syncthreads();
    int nw = blockDim.x >> 5;
    v = (tid < nw) ? sh[tid] : 0.0f;
    if (wid == 0) {
        #pragma unroll
        for (int o = 16; o; o >>= 1) v += __shfl_down_sync(0xffffffffu, v, o);
    }
    return v;
}

__global__ void zero_acc_kernel() {
    if (threadIdx.x < 3) g_acc[threadIdx.x] = 0.0;
}

// bilinear align_corners resize, both sides in one launch
__global__ void resize_kernel(const float* __restrict__ inL, const float* __restrict__ inR,
                              float* __restrict__ outL, float* __restrict__ outR,
                              int Hin, int Win, int Hout, int Wout) {
    int idx = blockIdx.x * blockDim.x + threadIdx.x;
    int total = 2 * BATCH * 3 * Hout * Wout;
    if (idx >= total) return;
    int i = idx % Wout; int t = idx / Wout;
    int j = t % Hout;   t /= Hout;
    int c = t % 3;      int b2 = t / 3;
    int side = (b2 >= BATCH);
    int b = b2 - side * BATCH;
    const float* in = side ? inR : inL;
    float* out = side ? outR : outL;

    float sy = (float)(Hin - 1) / (float)(Hout - 1);
    float sx = (float)(Win - 1) / (float)(Wout - 1);
    float y = j * sy, x = i * sx;
    int y0 = (int)floorf(y);
    int y1 = min(y0 + 1, Hin - 1);
    int x0 = (int)floorf(x);
    int x1 = min(x0 + 1, Win - 1);
    float wy = y - (float)y0;
    float wx = x - (float)x0;
    const float* p = in + ((long)(b * 3 + c) * Hin) * Win;
    float tl = p[y0 * Win + x0], tr = p[y0 * Win + x1];
    float bl = p[y1 * Win + x0], br = p[y1 * Win + x1];
    float top = tl * (1.f - wy) + bl * wy;
    float bot = tr * (1.f - wy) + br * wy;
    out[((long)(b * 3 + c) * Hout + j) * Wout + i] = top * (1.f - wx) + bot * wx;
}

// 1-D bilinear gather from a shared row, zero padding outside [0,W-1]
__device__ __forceinline__ float sample_sh(const float* __restrict__ row, float x, int W) {
    float x0f = floorf(x);
    int x0 = (int)x0f;
    float w1 = x - x0f;
    float v = 0.f;
    if (x0 >= 0 && x0 < W) v += row[x0] * (1.f - w1);
    int x1 = x0 + 1;
    if (x1 >= 0 && x1 < W) v += row[x1] * w1;
    return v;
}

// horizontal 3-sums for both stereo sides at shared index 'base'
__device__ __forceinline__ void hsum10(const float* __restrict__ Xl, const float* __restrict__ El,
                                       const float* __restrict__ Xr, const float* __restrict__ Er,
                                       int base, float* o) {
    float x0 = Xl[base - 1], x1 = Xl[base], x2 = Xl[base + 1];
    float e0 = El[base - 1], e1 = El[base], e2 = El[base + 1];
    o[0] = x0 + x1 + x2;
    o[1] = e0 + e1 + e2;
    o[2] = x0 * x0 + x1 * x1 + x2 * x2;
    o[3] = e0 * e0 + e1 * e1 + e2 * e2;
    o[4] = x0 * e0 + x1 * e1 + x2 * e2;
    float u0 = Xr[base - 1], u1 = Xr[base], u2 = Xr[base + 1];
    float v0 = Er[base - 1], v1 = Er[base], v2 = Er[base + 1];
    o[5] = u0 + u1 + u2;
    o[6] = v0 + v1 + v2;
    o[7] = u0 * u0 + u1 * u1 + u2 * u2;
    o[8] = v0 * v0 + v1 * v1 + v2 * v2;
    o[9] = u0 * v0 + u1 * v1 + u2 * v2;
}

__device__ __forceinline__ float ssim_val(float sx, float sy, float sxx, float syy, float sxy) {
    const float inv9 = 1.f / 9.f;
    float mux = sx * inv9, muy = sy * inv9;
    float sigx = sxx * inv9 - mux * mux;
    float sigy = syy * inv9 - muy * muy;
    float cov  = sxy * inv9 - mux * muy;
    float ssim = ((2.f * mux * muy + CC1) * (2.f * cov + CC2)) /
                 ((mux * mux + muy * muy + CC1) * (sigx + sigy + CC2));
    return fminf(fmaxf((1.f - ssim) * 0.5f, 0.f), 1.f);
}

// ---- channel-split fused kernel ----
// grid: (strips, BATCH, 3 channels). Each block: one channel's AP for APR rows.
// z==0 blocks additionally compute LR + DS (ch1/2 gradients via __ldg).
// shared: Dl, Dr, Xl, Xr, El, Er -- each (APR+2)*W
__global__ __launch_bounds__(NT, 2)
void ap_kernel(const float* __restrict__ lp, const float* __restrict__ rp,
               const float* __restrict__ disp,
               int H, int W, int lw, int APR,
               float coefS, float coefL, float coefLR, float coefDS) {
    extern __shared__ float sh[];
    int rows = APR + 2;
    int stride = rows * W;
    float* Dl = sh;
    float* Dr = Dl + stride;
    float* Xl = Dr + stride;
    float* Xr = Xl + stride;
    float* El = Xr + stride;
    float* Er = El + stride;

    int tid = threadIdx.x;
    int col = tid & (W - 1);
    int rg = tid >> lw;
    int G = NT >> lw;
    int b = blockIdx.y;
    int c = blockIdx.z;
    int r0 = blockIdx.x * APR;
    long hw = (long)H * W;
    const float* dlg = disp + (long)b * 2 * hw;
    const float* drg = dlg + hw;
    const float* Lg = lp + (long)(b * 3 + c) * hw;
    const float* Rg = rp + (long)(b * 3 + c) * hw;
    float Wm1 = (float)(W - 1);

    // ---- phase A: stage disp + this channel's planes ----
    for (int r = rg; r < rows; r += G) {
        int gj = r0 - 1 + r;
        bool in = (gj >= 0 && gj < H);
        long o = (long)gj * W + col;
        int so = r * W + col;
        Dl[so] = in ? dlg[o] : 0.f;
        Dr[so] = in ? drg[o] : 0.f;
        Xl[so] = in ? Lg[o] : 0.f;
        Xr[so] = in ? Rg[o] : 0.f;
    }
    __syncthreads();

    float accAP = 0.f;

    // ---- phase B: warp estimates from shared + L1 term ----
    for (int r = rg; r < rows; r += G) {
        int gj = r0 - 1 + r;
        int so = r * W + col;
        float el = 0.f, er = 0.f;
        if (gj >= 0 && gj < H) {
            float dlv = Dl[so], drv = Dr[so];
            el = sample_sh(Xr + r * W, (float)col - dlv * Wm1, W);
            er = sample_sh(Xl + r * W, (float)col + drv * Wm1, W);
            if (r >= 1 && r <= APR)
                accAP += coefL * (fabsf(Xl[so] - el) + fabsf(Xr[so] - er));
        }
        El[so] = el;
        Er[so] = er;
    }
    __syncthreads();

    // ---- phase C: separable SSIM ----
    if (col >= 1 && col <= W - 2) {
        if (G == 1) {
            float a0[10], a1[10], a2[10];
            hsum10(Xl, El, Xr, Er, col, a0);
            hsum10(Xl, El, Xr, Er, W + col, a1);
            for (int r = 1; r <= APR; r++) {
                hsum10(Xl, El, Xr, Er, (r + 1) * W + col, a2);
                int gj = r0 + r - 1;
                if (gj >= 1 && gj <= H - 2) {
                    float v = ssim_val(a0[0] + a1[0] + a2[0], a0[1] + a1[1] + a2[1],
                                       a0[2] + a1[2] + a2[2], a0[3] + a1[3] + a2[3],
                                       a0[4] + a1[4] + a2[4]);
                    v += ssim_val(a0[5] + a1[5] + a2[5], a0[6] + a1[6] + a2[6],
                                  a0[7] + a1[7] + a2[7], a0[8] + a1[8] + a2[8],
                                  a0[9] + a1[9] + a2[9]);
                    accAP += coefS * v;
                }
                #pragma unroll
                for (int k = 0; k < 10; k++) { a0[k] = a1[k]; a1[k] = a2[k]; }
            }
        } else {
            for (int r = 1 + rg; r <= APR; r += G) {
                int gj = r0 + r - 1;
                if (gj >= 1 && gj <= H - 2) {
                    float a0[10], a1[10], a2[10];
                    hsum10(Xl, El, Xr, Er, (r - 1) * W + col, a0);
                    hsum10(Xl, El, Xr, Er, r * W + col, a1);
                    hsum10(Xl, El, Xr, Er, (r + 1) * W + col, a2);
                    float v = ssim_val(a0[0] + a1[0] + a2[0], a0[1] + a1[1] + a2[1],
                                       a0[2] + a1[2] + a2[2], a0[3] + a1[3] + a2[3],
                                       a0[4] + a1[4] + a2[4]);
                    v += ssim_val(a0[5] + a1[5] + a2[5], a0[6] + a1[6] + a2[6],
                                  a0[7] + a1[7] + a2[7], a0[8] + a1[8] + a2[8],
                                  a0[9] + a1[9] + a2[9]);
                    accAP += coefS * v;
                }
            }
        }
    }

    float s0 = blockReduce(accAP);
    if (tid == 0) atomicAdd(&g_acc[0], (double)s0);

    // ---- phase D (z==0 only): LR consistency + edge-aware smoothness ----
    if (c == 0) {
        const float* L1g = lp + (long)(b * 3 + 1) * hw;
        const float* L2g = lp + (long)(b * 3 + 2) * hw;
        const float* R1g = rp + (long)(b * 3 + 1) * hw;
        const float* R2g = rp + (long)(b * 3 + 2) * hw;
        float accLR = 0.f, accDS = 0.f;
        const float third = 1.f / 3.f;
        for (int r = 1 + rg; r <= APR; r += G) {
            int gj = r0 + r - 1;
            if (gj >= H) continue;
            int so = r * W + col;
            long o = (long)gj * W + col;
            float dlv = Dl[so], drv = Dr[so];
            float r2l = sample_sh(Dr + r * W, (float)col - dlv * Wm1, W);
            float l2r = sample_sh(Dl + r * W, (float)col + drv * Wm1, W);
            accLR += fabsf(dlv - r2l) + fabsf(drv - l2r);

            if (col < W - 1) {
                float aL = fabsf(Xl[so] - Xl[so + 1])
                         + fabsf(__ldg(L1g + o) - __ldg(L1g + o + 1))
                         + fabsf(__ldg(L2g + o) - __ldg(L2g + o + 1));
                float aR = fabsf(Xr[so] - Xr[so + 1])
                         + fabsf(__ldg(R1g + o) - __ldg(R1g + o + 1))
                         + fabsf(__ldg(R2g + o) - __ldg(R2g + o + 1));
                accDS += fabsf(dlv - Dl[so + 1]) * __expf(-aL * third)
                       + fabsf(drv - Dr[so + 1]) * __expf(-aR * third);
            }
            if (gj < H - 1) {
                float aL = fabsf(Xl[so] - Xl[so + W])
                         + fabsf(__ldg(L1g + o) - __ldg(L1g + o + W))
                         + fabsf(__ldg(L2g + o) - __ldg(L2g + o + W));
                float aR = fabsf(Xr[so] - Xr[so + W])
                         + fabsf(__ldg(R1g + o) - __ldg(R1g + o + W))
                         + fabsf(__ldg(R2g + o) - __ldg(R2g + o + W));
                accDS += fabsf(dlv - Dl[so + W]) * __expf(-aL * third)
                       + fabsf(drv - Dr[so + W]) * __expf(-aR * third);
            }
        }
        __syncthreads();
        float s1 = blockReduce(accLR);
        if (tid == 0) atomicAdd(&g_acc[1], (double)(coefLR * s1));
        __syncthreads();
        float s2 = blockReduce(accDS);
        if (tid == 0) atomicAdd(&g_acc[2], (double)(coefDS * s2));
    }
}

__global__ void finalize_kernel(float* __restrict__ out) {
    float AP = (float)g_acc[0];
    float LR = (float)g_acc[1];
    float DS = (float)g_acc[2];
    out[0] = AP + LR + DS;
    out[1] = AP;
    out[2] = LR;
    out[3] = DS;
}

// -------------------- host --------------------
extern "C" void kernel_launch(void* const* d_in, const int* in_sizes, int n_in,
                              void* d_out, int out_size) {
    const float* disp[4];
    for (int i = 0; i < 4; i++) disp[i] = (const float*)d_in[i];
    const float* left = (const float*)d_in[4];
    const float* right = (const float*)d_in[5];

    float *pl, *pr;
    cudaGetSymbolAddress((void**)&pl, g_pyr_l);
    cudaGetSymbolAddress((void**)&pr, g_pyr_r);

    const int H = 256, W = 512;
    const int TB = 256;

    cudaFuncSetAttribute(ap_kernel, cudaFuncAttributeMaxDynamicSharedMemorySize, 100 * 1024);

    zero_acc_kernel<<<1, 32>>>();

    const float* lp[4];
    const float* rp[4];
    lp[0] = left; rp[0] = right;
    float* lbuf[4] = {nullptr, pl + OFF_L1, pl + OFF_L2, pl + OFF_L3};
    float* rbuf[4] = {nullptr, pr + OFF_L1, pr + OFF_L2, pr + OFF_L3};

    for (int i = 1; i < 4; i++) {
        int hin = H >> (i - 1), win = W >> (i - 1);
        int ho = H >> i, wo = W >> i;
        int tot = 2 * BATCH * 3 * ho * wo;
        int grid = (tot + TB - 1) / TB;
        resize_kernel<<<grid, TB>>>(lp[i - 1], rp[i - 1], lbuf[i], rbuf[i], hin, win, ho, wo);
        lp[i] = lbuf[i];
        rp[i] = rbuf[i];
    }

    const int APRv[4] = {6, 8, 16, 32};
    const int LWv[4] = {9, 8, 7, 6};

    for (int i = 0; i < 4; i++) {
        int h = H >> i, w = W >> i;
        int totI = BATCH * 3 * h * w;
        int totD = BATCH * h * w;

        float coefS = (A_AP * A_AP) / ((float)BATCH * 3.f * (float)(h - 2) * (float)(w - 2));
        float coefL = (A_AP * (1.f - A_AP)) / (float)totI;
        float coefLR = 1.0f / (float)totD;
        float coefDS = A_DS / ((float)totD * (float)(1 << i));

        int APR = APRv[i];
        int strips = (h + APR - 1) / APR;
        size_t smem = (size_t)6 * (APR + 2) * w * sizeof(float);
        dim3 grd(strips, BATCH, 3);
        ap_kernel<<<grd, NT, smem>>>(lp[i], rp[i], disp[i], h, w, LWv[i], APR,
                                     coefS, coefL, coefLR, coefDS);
    }

    finalize_kernel<<<1, 1>>>((float*)d_out);
}